// round 10
// baseline (speedup 1.0000x reference)
#include <cuda_runtime.h>

// ---------------- problem sizes ----------------
#define NC 100000
#define NT 300000
#define NP 50000
#define EM 300000
#define EI 600000
#define ET (EM + EI)
#define NOUT 10

// ---------------- scratch, grouped by producer ----------------
// G1: P1a targets (customer/product side — feeds phase2)
#define OFF_MCS   0                               // [NC*8] sum x_t over c's transactions
#define OFF_MPS   (OFF_MCS + (size_t)NC * 8)      // [NP*8] sum x_t over p's transactions
#define OFF_CMC   (OFF_MPS + (size_t)NP * 8)      // [NC] deg(c)
#define OFF_CIP   (OFF_CMC + NC)                  // [NP] deg(p)
#define G1_END    (OFF_CIP + NP)
// G2: P1b targets (transaction side — feeds final)
#define OFF_MTC   G1_END                          // [NT*8] sum x_c over t's customers
#define OFF_MTP   (OFF_MTC + (size_t)NT * 8)      // [NT*8] sum x_p over t's products
#define OFF_CMT   (OFF_MTP + (size_t)NT * 8)      // [NT] deg(t, makes)
#define OFF_CIT   (OFF_CMT + NT)                  // [NT] deg(t, in)
#define G2_END    (OFF_CIT + NT)
// G3: phase2 targets
#define OFF_MMC   G2_END                          // [NT*8]
#define OFF_MMP   (OFF_MMC + (size_t)NT * 8)      // [NT*8]
#define SCR_TOTAL (OFF_MMP + (size_t)NT * 8)

__device__ float g_scr[SCR_TOTAL];

// ---------------- weight-prep scratch ----------------
__device__ float g_m1[7][1024];
__device__ float g_r1[7][128];
__device__ float g_m2[5][1024];
__device__ float g_r2[5][128];
__device__ float g_G[400];
__device__ float g_g[50];

// ---------------- weight prep (parallelized closed-form chain) ----------------
__global__ void prep1(const float* __restrict__ Wc, const float* __restrict__ bc,
                      const float* __restrict__ Wn, const float* __restrict__ Wr,
                      const float* __restrict__ bl) {
    int b = blockIdx.x, col = threadIdx.x;   // 128 threads
    if (b < 7) {
        int X = 0; const float* M1 = Wn; const float* M2 = nullptr; float s = 1.f;
        switch (b) {
            case 0: X = 1; M1 = Wr;             M2 = Wr + 2 * 16384; s = 0.5f; break;
            case 1: X = 0; M1 = Wn;             s = 0.5f; break;
            case 2: X = 2; M1 = Wn + 2 * 16384; s = 0.5f; break;
            case 3: X = 0; M1 = Wr + 1 * 16384; break;
            case 4: X = 1; M1 = Wn + 1 * 16384; break;
            case 5: X = 2; M1 = Wr + 3 * 16384; break;
            case 6: X = 1; M1 = Wn + 3 * 16384; break;
        }
        #pragma unroll 2
        for (int f = 0; f < 8; f++) {
            float acc = 0.f;
            #pragma unroll 4
            for (int d = 0; d < 16; d++) {
                int k = f * 16 + d;
                float m = M1[k * 128 + col];
                if (M2) m += M2[k * 128 + col];
                acc += Wc[X * 128 + k] * m;
            }
            g_m1[b][f * 128 + col] = s * acc;
        }
    } else {
        int r = b - 7;
        float acc = 0.f;
        switch (r) {
            case 0:
                #pragma unroll 8
                for (int k = 0; k < 128; k++) acc += bc[k] * Wn[k * 128 + col];
                g_r1[0][col] = 0.5f * acc; break;
            case 1:
                #pragma unroll 8
                for (int k = 0; k < 128; k++) acc += bc[256 + k] * Wn[2 * 16384 + k * 128 + col];
                g_r1[1][col] = 0.5f * acc; break;
            case 2:
                #pragma unroll 8
                for (int k = 0; k < 128; k++)
                    acc += bc[128 + k] * (Wr[k * 128 + col] + Wr[2 * 16384 + k * 128 + col]);
                g_r1[2][col] = 0.5f * (acc + bl[0 * 128 + col] + bl[2 * 128 + col]); break;
            case 3:
                #pragma unroll 8
                for (int k = 0; k < 128; k++) acc += bc[128 + k] * Wn[1 * 16384 + k * 128 + col];
                g_r1[3][col] = acc; break;
            case 4:
                #pragma unroll 8
                for (int k = 0; k < 128; k++) acc += bc[k] * Wr[1 * 16384 + k * 128 + col];
                g_r1[4][col] = acc + bl[1 * 128 + col]; break;
            case 5:
                #pragma unroll 8
                for (int k = 0; k < 128; k++) acc += bc[128 + k] * Wn[3 * 16384 + k * 128 + col];
                g_r1[5][col] = acc; break;
            case 6:
                #pragma unroll 8
                for (int k = 0; k < 128; k++) acc += bc[256 + k] * Wr[3 * 16384 + k * 128 + col];
                g_r1[6][col] = acc + bl[3 * 128 + col]; break;
        }
    }
}

__global__ void prep2(const float* __restrict__ Wn, const float* __restrict__ Wr,
                      const float* __restrict__ bl) {
    int b = blockIdx.x, col = threadIdx.x;   // 128 threads
    const float* Un = Wn + 4 * 16384;
    const float* Vn = Wn + 6 * 16384;
    const float* R0 = Wr + 4 * 16384;
    const float* R2 = Wr + 6 * 16384;
    if (b < 40) {
        int m = b >> 3, f = b & 7;
        float acc = 0.f;
        #pragma unroll 4
        for (int k = 0; k < 128; k++) {
            float w = 0.f;
            switch (m) {
                case 0: w = g_m1[0][f * 128 + k] * 0.5f * (R0[k * 128 + col] + R2[k * 128 + col]); break;
                case 1: w = g_m1[3][f * 128 + k] * 0.5f * Un[k * 128 + col]
                          + g_m1[1][f * 128 + k] * 0.5f * (R0[k * 128 + col] + R2[k * 128 + col]); break;
                case 2: w = g_m1[5][f * 128 + k] * 0.5f * Vn[k * 128 + col]
                          + g_m1[2][f * 128 + k] * 0.5f * (R0[k * 128 + col] + R2[k * 128 + col]); break;
                case 3: w = g_m1[4][f * 128 + k] * 0.5f * Un[k * 128 + col]; break;
                case 4: w = g_m1[6][f * 128 + k] * 0.5f * Vn[k * 128 + col]; break;
            }
            acc += w;
        }
        g_m2[m][f * 128 + col] = acc;
    } else {
        int r = b - 40;
        float acc = 0.f;
        #pragma unroll 4
        for (int k = 0; k < 128; k++) {
            float U = 0.5f * Un[k * 128 + col];
            float V = 0.5f * Vn[k * 128 + col];
            float R = 0.5f * (R0[k * 128 + col] + R2[k * 128 + col]);
            switch (r) {
                case 0: acc += g_r1[3][k] * U; break;
                case 1: acc += g_r1[5][k] * V; break;
                case 2: acc += g_r1[4][k] * U + g_r1[0][k] * R; break;
                case 3: acc += g_r1[6][k] * V + g_r1[1][k] * R; break;
                case 4: acc += g_r1[2][k] * R; break;
            }
        }
        if (r == 4) acc += 0.5f * (bl[4 * 128 + col] + bl[6 * 128 + col]);
        g_r2[r][col] = acc;
    }
}

__global__ void prep3(const float* __restrict__ Wout, const float* __restrict__ bout) {
    int tid = threadIdx.x;   // 512
    if (tid < 400) {
        int m = tid / 80, f = (tid % 80) / 10, o = tid % 10;
        float acc = 0.f;
        #pragma unroll 8
        for (int k = 0; k < 128; k++) acc += g_m2[m][f * 128 + k] * Wout[k * 10 + o];
        g_G[(m * 8 + f) * 10 + o] = acc;
    } else if (tid < 450) {
        int r = (tid - 400) / 10, o = (tid - 400) % 10;
        float acc = 0.f;
        #pragma unroll 8
        for (int k = 0; k < 128; k++) acc += g_r2[r][k] * Wout[k * 10 + o];
        if (r == 4) acc += bout[o];
        g_g[r * 10 + o] = acc;
    }
}

// ---------------- atomics ----------------
__device__ __forceinline__ void red_add_v4(float* addr, float4 v) {
    asm volatile("red.global.add.v4.f32 [%0], {%1,%2,%3,%4};"
                 :: "l"(addr), "f"(v.x), "f"(v.y), "f"(v.z), "f"(v.w)
                 : "memory");
}
__device__ __forceinline__ void red_add_f(float* addr, float v) {
    asm volatile("red.global.add.f32 [%0], %1;" :: "l"(addr), "f"(v) : "memory");
}

// ---------------- P1a: x_t -> customer/product sums + degrees (feeds phase2) ----------------
__global__ __launch_bounds__(256)
void p1a(const float* __restrict__ x_t,
         const int* __restrict__ em_src, const int* __restrict__ em_dst,
         const int* __restrict__ ei_src, const int* __restrict__ ei_dst,
         float* __restrict__ scr) {
    int e = blockIdx.x * blockDim.x + threadIdx.x;
    const int *src, *dst;
    float *agg, *cnt;
    if (e < EM) {
        src = em_src; dst = em_dst;
        agg = scr + OFF_MCS; cnt = scr + OFF_CMC;
    } else if (e < ET) {
        e -= EM;
        src = ei_src; dst = ei_dst;
        agg = scr + OFF_MPS; cnt = scr + OFF_CIP;
    } else return;
    int s = __ldg(src + e);
    int d = __ldg(dst + e);
    const float4* pd = (const float4*)(x_t + (size_t)d * 8);
    float4 v0 = pd[0], v1 = pd[1];
    float* o = agg + (size_t)s * 8;
    red_add_v4(o,     v0);
    red_add_v4(o + 4, v1);
    red_add_f(cnt + s, 1.0f);
}

// ---------------- P1b: x_c/x_p -> transaction sums + degrees (feeds final) ----------------
__global__ __launch_bounds__(256)
void p1b(const float* __restrict__ x_c, const float* __restrict__ x_p,
         const int* __restrict__ em_src, const int* __restrict__ em_dst,
         const int* __restrict__ ei_src, const int* __restrict__ ei_dst,
         float* __restrict__ scr) {
    int e = blockIdx.x * blockDim.x + threadIdx.x;
    const int *src, *dst;
    const float* xs;
    float *agg, *cnt;
    if (e < EM) {
        src = em_src; dst = em_dst; xs = x_c;
        agg = scr + OFF_MTC; cnt = scr + OFF_CMT;
    } else if (e < ET) {
        e -= EM;
        src = ei_src; dst = ei_dst; xs = x_p;
        agg = scr + OFF_MTP; cnt = scr + OFF_CIT;
    } else return;
    int s = __ldg(src + e);
    int d = __ldg(dst + e);
    const float4* ps = (const float4*)(xs + (size_t)s * 8);
    float4 v0 = ps[0], v1 = ps[1];
    float* o = agg + (size_t)d * 8;
    red_add_v4(o,     v0);
    red_add_v4(o + 4, v1);
    red_add_f(cnt + d, 1.0f);
}

// ---------------- phase 2: mean of c/p-sums -> transaction 2-hop sums ----------------
__global__ __launch_bounds__(256)
void phase2all(const int* __restrict__ em_src, const int* __restrict__ em_dst,
               const int* __restrict__ ei_src, const int* __restrict__ ei_dst,
               float* __restrict__ scr) {
    int e = blockIdx.x * blockDim.x + threadIdx.x;
    const int *src, *dst;
    const float *msum, *cnt;
    float* mm;
    if (e < EM) {
        src = em_src; dst = em_dst;
        msum = scr + OFF_MCS; cnt = scr + OFF_CMC; mm = scr + OFF_MMC;
    } else if (e < ET) {
        e -= EM;
        src = ei_src; dst = ei_dst;
        msum = scr + OFF_MPS; cnt = scr + OFF_CIP; mm = scr + OFF_MMP;
    } else return;
    int s = __ldg(src + e);
    int d = __ldg(dst + e);
    float c  = __ldg(cnt + s);
    float iv = 1.0f / fmaxf(c, 1.0f);
    const float4* pm = (const float4*)(msum + (size_t)s * 8);
    float4 v0 = pm[0], v1 = pm[1];
    v0.x *= iv; v0.y *= iv; v0.z *= iv; v0.w *= iv;
    v1.x *= iv; v1.y *= iv; v1.z *= iv; v1.w *= iv;
    float* o = mm + (size_t)d * 8;
    red_add_v4(o,     v0);
    red_add_v4(o + 4, v1);
}

// ---------------- final: 40-feature linear model + degree gates + softmax ----------------
__global__ __launch_bounds__(256)
void final_kernel(const float* __restrict__ xt, float* __restrict__ out) {
    __shared__ float sG[400];
    __shared__ float sg[50];
    int tid = threadIdx.x;
    for (int i = tid; i < 400; i += 256) sG[i] = g_G[i];
    if (tid < 50) sg[tid] = g_g[tid];
    __syncthreads();

    int t = blockIdx.x * 256 + tid;
    if (t >= NT) return;

    float cm = g_scr[OFF_CMT + t], ci = g_scr[OFF_CIT + t];
    float im = 1.f / fmaxf(cm, 1.f);
    float ii = 1.f / fmaxf(ci, 1.f);
    float dm = cm > 0.f ? 1.f : 0.f;
    float di = ci > 0.f ? 1.f : 0.f;

    float feat[40];
    {
        const float4* p;
        float4 a, b;
        p = (const float4*)(xt + (size_t)t * 8); a = p[0]; b = p[1];
        feat[0]=a.x; feat[1]=a.y; feat[2]=a.z; feat[3]=a.w;
        feat[4]=b.x; feat[5]=b.y; feat[6]=b.z; feat[7]=b.w;
        p = (const float4*)(g_scr + OFF_MTC + (size_t)t * 8); a = p[0]; b = p[1];
        feat[8]=a.x*im; feat[9]=a.y*im; feat[10]=a.z*im; feat[11]=a.w*im;
        feat[12]=b.x*im; feat[13]=b.y*im; feat[14]=b.z*im; feat[15]=b.w*im;
        p = (const float4*)(g_scr + OFF_MTP + (size_t)t * 8); a = p[0]; b = p[1];
        feat[16]=a.x*ii; feat[17]=a.y*ii; feat[18]=a.z*ii; feat[19]=a.w*ii;
        feat[20]=b.x*ii; feat[21]=b.y*ii; feat[22]=b.z*ii; feat[23]=b.w*ii;
        p = (const float4*)(g_scr + OFF_MMC + (size_t)t * 8); a = p[0]; b = p[1];
        feat[24]=a.x*im; feat[25]=a.y*im; feat[26]=a.z*im; feat[27]=a.w*im;
        feat[28]=b.x*im; feat[29]=b.y*im; feat[30]=b.z*im; feat[31]=b.w*im;
        p = (const float4*)(g_scr + OFF_MMP + (size_t)t * 8); a = p[0]; b = p[1];
        feat[32]=a.x*ii; feat[33]=a.y*ii; feat[34]=a.z*ii; feat[35]=a.w*ii;
        feat[36]=b.x*ii; feat[37]=b.y*ii; feat[38]=b.z*ii; feat[39]=b.w*ii;
    }

    float p[NOUT];
    #pragma unroll
    for (int o = 0; o < NOUT; o++) {
        float s = sg[40 + o];
        s = fmaf(dm, sg[o]      + sg[20 + o], s);
        s = fmaf(di, sg[10 + o] + sg[30 + o], s);
        p[o] = s;
    }
    #pragma unroll
    for (int f = 0; f < 40; f++) {
        float xv = feat[f];
        #pragma unroll
        for (int o = 0; o < NOUT; o++) p[o] = fmaf(xv, sG[f * 10 + o], p[o]);
    }

    float m = p[0];
    #pragma unroll
    for (int o = 1; o < NOUT; o++) m = fmaxf(m, p[o]);
    float sum = 0.f;
    #pragma unroll
    for (int o = 0; o < NOUT; o++) { p[o] = expf(p[o] - m); sum += p[o]; }
    float isum = 1.0f / sum;
    #pragma unroll
    for (int o = 0; o < NOUT; o++) out[(size_t)t * NOUT + o] = p[o] * isum;
}

// ---------------- host orchestration ----------------
extern "C" void kernel_launch(void* const* d_in, const int* in_sizes, int n_in,
                              void* d_out, int out_size) {
    const float* x_c   = (const float*)d_in[0];
    const float* x_t   = (const float*)d_in[1];
    const float* x_p   = (const float*)d_in[2];
    const float* W_col = (const float*)d_in[3];
    const float* b_col = (const float*)d_in[4];
    const float* Wn    = (const float*)d_in[5];
    const float* Wr    = (const float*)d_in[6];
    const float* b_lin = (const float*)d_in[7];
    const float* W_out = (const float*)d_in[8];
    const float* b_out = (const float*)d_in[9];
    const int* em_src  = (const int*)d_in[10];
    const int* em_dst  = (const int*)d_in[11];
    const int* ei_src  = (const int*)d_in[12];
    const int* ei_dst  = (const int*)d_in[13];
    float* out = (float*)d_out;

    float* scr;
    cudaGetSymbolAddress((void**)&scr, g_scr);
    const int GE = (ET + 255) / 256;

    cudaStream_t s2, s3;
    cudaEvent_t evFork, evG3, evP1b, evPrep;
    bool forked = (cudaStreamCreateWithFlags(&s2, cudaStreamNonBlocking) == cudaSuccess) &&
                  (cudaStreamCreateWithFlags(&s3, cudaStreamNonBlocking) == cudaSuccess) &&
                  (cudaEventCreateWithFlags(&evFork, cudaEventDisableTiming) == cudaSuccess) &&
                  (cudaEventCreateWithFlags(&evG3,   cudaEventDisableTiming) == cudaSuccess) &&
                  (cudaEventCreateWithFlags(&evP1b,  cudaEventDisableTiming) == cudaSuccess) &&
                  (cudaEventCreateWithFlags(&evPrep, cudaEventDisableTiming) == cudaSuccess);

    if (forked) {
        cudaEventRecord(evFork, 0);
        cudaStreamWaitEvent(s2, evFork, 0);
        cudaStreamWaitEvent(s3, evFork, 0);

        // s2: zero G2 -> P1b (transaction-side aggregates; joined at final)
        cudaMemsetAsync(scr + G1_END, 0, (G2_END - G1_END) * sizeof(float), s2);
        p1b<<<GE, 256, 0, s2>>>(x_c, x_p, em_src, em_dst, ei_src, ei_dst, scr);
        cudaEventRecord(evP1b, s2);

        // s3: zero G3 (phase2 targets) -> weight-prep chain
        cudaMemsetAsync(scr + G2_END, 0, (SCR_TOTAL - G2_END) * sizeof(float), s3);
        cudaEventRecord(evG3, s3);
        prep1<<<14, 128, 0, s3>>>(W_col, b_col, Wn, Wr, b_lin);
        prep2<<<45, 128, 0, s3>>>(Wn, Wr, b_lin);
        prep3<<<1, 512, 0, s3>>>(W_out, b_out);
        cudaEventRecord(evPrep, s3);

        // main: zero G1 -> P1a -> (G3 ready) phase2 -> (P1b + preps ready) final
        cudaMemsetAsync(scr, 0, G1_END * sizeof(float));
        p1a<<<GE, 256>>>(x_t, em_src, em_dst, ei_src, ei_dst, scr);
        cudaStreamWaitEvent(0, evG3, 0);
        phase2all<<<GE, 256>>>(em_src, em_dst, ei_src, ei_dst, scr);
        cudaStreamWaitEvent(0, evP1b, 0);
        cudaStreamWaitEvent(0, evPrep, 0);
        final_kernel<<<(NT + 255) / 256, 256>>>(x_t, out);

        cudaStreamDestroy(s2);
        cudaStreamDestroy(s3);
        cudaEventDestroy(evFork);
        cudaEventDestroy(evG3);
        cudaEventDestroy(evP1b);
        cudaEventDestroy(evPrep);
    } else {
        cudaMemsetAsync(scr, 0, SCR_TOTAL * sizeof(float));
        prep1<<<14, 128>>>(W_col, b_col, Wn, Wr, b_lin);
        prep2<<<45, 128>>>(Wn, Wr, b_lin);
        prep3<<<1, 512>>>(W_out, b_out);
        p1a<<<GE, 256>>>(x_t, em_src, em_dst, ei_src, ei_dst, scr);
        p1b<<<GE, 256>>>(x_c, x_p, em_src, em_dst, ei_src, ei_dst, scr);
        phase2all<<<GE, 256>>>(em_src, em_dst, ei_src, ei_dst, scr);
        final_kernel<<<(NT + 255) / 256, 256>>>(x_t, out);
    }
}